// round 2
// baseline (speedup 1.0000x reference)
#include <cuda_runtime.h>
#include <math.h>

#define HW       2304      // 48*48
#define NPIX     9216      // 96*96
#define XT_SLAB  294912    // 48*48*128
#define K_SLAB   73728     // 48*48*32
#define QUP_SLAB 294912    // 96*96*32

__device__ __align__(128) float g_xt [4*XT_SLAB];   // x channel-last per (b,g)
__device__ __align__(128) float g_k  [4*K_SLAB];    // k channel-last per (b,g)
__device__ __align__(128) float g_q  [4*K_SLAB];    // q lowres channel-last
__device__ __align__(128) float g_qup[4*QUP_SLAB];  // q upsampled channel-last
__device__ __align__(128) float g_t  [4*QUP_SLAB];  // gelu(ln(dwconv(q_up)))
__device__ __align__(128) float g_crd[4*NPIX*18];   // (iy,ix) per (bg,pix,tap)
__device__ float g_mu[2*HW], g_rstd[2*HW];
__device__ __align__(128) float g_WT[256*128];      // [c][o]; o<64: Wq, o>=64: Wk (LN-gain folded)
__device__ float g_csum[128], g_bias2[128];
__device__ __align__(128) float g_w2[2*32*9*12];    // [half][c][tapk][j(pad12)]

// ---------------- k0: fold LN into weights, transpose offset weights ----------
__global__ void k0_prep(const float* __restrict__ Wq, const float* __restrict__ Wk,
                        const float* __restrict__ g, const float* __restrict__ b,
                        const float* __restrict__ off_w)
{
    int t = threadIdx.x; // 256
    for (int idx = t; idx < 256*128; idx += 256) {
        int c = idx >> 7, o = idx & 127;
        float w = (o < 64) ? Wq[o*256 + c] : Wk[(o-64)*256 + c];
        g_WT[idx] = w * g[c];
    }
    for (int i = t; i < 2*32*9*12; i += 256) {
        int j = i % 12; int k = (i/12) % 9; int c = (i/108) % 32; int half = i/3456;
        g_w2[i] = (j < 9) ? off_w[((j*2+half)*32 + c)*9 + k] : 0.f;
    }
    __shared__ float scs[256], sbs[256];
    {
        int o = t >> 1, hf = t & 1;
        const float* Wr = (o < 64) ? (Wq + o*256) : (Wk + (o-64)*256);
        float cs = 0.f, bs = 0.f;
        for (int c = hf*128; c < hf*128 + 128; c++) { cs += Wr[c]*g[c]; bs += Wr[c]*b[c]; }
        scs[t] = cs; sbs[t] = bs;
    }
    __syncthreads();
    if (t < 128) { g_csum[t] = scs[2*t] + scs[2*t+1]; g_bias2[t] = sbs[2*t] + sbs[2*t+1]; }
}

// ---------------- k1: transpose x to channel-last + LN stats ------------------
__global__ void k1_tr(const float* __restrict__ x)
{
    __shared__ float xs[128*49];
    __shared__ float ssum[48], ssq[48];
    int b = blockIdx.x / 48, y = blockIdx.x % 48;
    int t = threadIdx.x; // 256
    if (t < 48) { ssum[t] = 0.f; ssq[t] = 0.f; }
    int wid = t >> 5, lane = t & 31;
    for (int half = 0; half < 2; half++) {
        __syncthreads();
        const float* src = x + ((size_t)(b*256 + half*128))*HW + y*48;
        for (int idx = t; idx < 128*48; idx += 256) {
            int c = idx / 48, xx = idx - c*48;
            xs[c*49 + xx] = src[(size_t)c*HW + xx];
        }
        __syncthreads();
        for (int xx = wid; xx < 48; xx += 8) {
            float s = 0.f, q = 0.f;
            #pragma unroll
            for (int j = 0; j < 4; j++) { float v = xs[(lane + 32*j)*49 + xx]; s += v; q += v*v; }
            #pragma unroll
            for (int o = 16; o; o >>= 1) { s += __shfl_xor_sync(0xffffffffu, s, o); q += __shfl_xor_sync(0xffffffffu, q, o); }
            if (lane == 0) { ssum[xx] += s; ssq[xx] += q; }
        }
        float* dst = g_xt + ((size_t)(b*2 + half))*XT_SLAB + (size_t)y*48*128;
        for (int idx = t; idx < 128*48; idx += 256) {
            int xx = idx >> 7, c = idx & 127;
            dst[xx*128 + c] = xs[c*49 + xx];
        }
    }
    __syncthreads();
    if (t < 48) {
        float mu = ssum[t] * (1.0f/256.0f);
        float var = ssq[t] * (1.0f/256.0f) - mu*mu;
        int p = b*HW + y*48 + t;
        g_mu[p] = mu;
        g_rstd[p] = rsqrtf(var + 1e-5f);
    }
}

// ---------------- k2: Q/K projection ------------------------------------------
__global__ void k2_qk()
{
    int bid = blockIdx.x;                // 192 blocks: (b, y, half-row)
    int xh = bid & 1; int y = (bid >> 1) % 48; int b = bid / 96;
    int t = threadIdx.x;                 // 96 threads
    int pg = t >> 4;                     // 0..5
    int og = t & 15;                     // 0..15
    int px0 = xh*24 + pg*4;
    int o0 = og*8;
    const float* x0 = g_xt + (size_t)(b*2)*XT_SLAB + (size_t)y*48*128;
    float acc[4][8];
    #pragma unroll
    for (int i = 0; i < 4; i++)
        #pragma unroll
        for (int j = 0; j < 8; j++) acc[i][j] = 0.f;

    #pragma unroll 4
    for (int c = 0; c < 256; c++) {
        float4 w0 = *(const float4*)&g_WT[c*128 + o0];
        float4 w1 = *(const float4*)&g_WT[c*128 + o0 + 4];
        int coff = ((c >> 7) * XT_SLAB) + (c & 127);
        #pragma unroll
        for (int i = 0; i < 4; i++) {
            float xv = x0[(px0 + i)*128 + coff];
            acc[i][0] += xv*w0.x; acc[i][1] += xv*w0.y; acc[i][2] += xv*w0.z; acc[i][3] += xv*w0.w;
            acc[i][4] += xv*w1.x; acc[i][5] += xv*w1.y; acc[i][6] += xv*w1.z; acc[i][7] += xv*w1.w;
        }
    }
    float csA[8], bsA[8];
    #pragma unroll
    for (int j = 0; j < 8; j++) { csA[j] = g_csum[o0+j]; bsA[j] = g_bias2[o0+j]; }

    int isK = (o0 >= 64);
    int oo  = o0 & 63;
    int grp = oo >> 5, cl0 = oo & 31;
    float* dst = (isK ? g_k : g_q) + (size_t)(b*2 + grp)*K_SLAB;
    #pragma unroll
    for (int i = 0; i < 4; i++) {
        int p = y*48 + px0 + i;
        float mu = g_mu[b*HW + p], rs = g_rstd[b*HW + p];
        float4 v0, v1;
        v0.x = rs*(acc[i][0] - mu*csA[0]) + bsA[0];
        v0.y = rs*(acc[i][1] - mu*csA[1]) + bsA[1];
        v0.z = rs*(acc[i][2] - mu*csA[2]) + bsA[2];
        v0.w = rs*(acc[i][3] - mu*csA[3]) + bsA[3];
        v1.x = rs*(acc[i][4] - mu*csA[4]) + bsA[4];
        v1.y = rs*(acc[i][5] - mu*csA[5]) + bsA[5];
        v1.z = rs*(acc[i][6] - mu*csA[6]) + bsA[6];
        v1.w = rs*(acc[i][7] - mu*csA[7]) + bsA[7];
        *(float4*)&dst[p*32 + cl0]     = v0;
        *(float4*)&dst[p*32 + cl0 + 4] = v1;
    }
}

// ---------------- k3: bilinear resize q 48 -> 96 (align_corners) --------------
__global__ void k3_resize()
{
    int idx = blockIdx.x*256 + threadIdx.x;   // 4*9216*8
    int c4 = idx & 7; int r = idx >> 3;
    int ox = r % 96; r /= 96; int oy = r % 96; int bg = r / 96;
    const float R = 47.0f/95.0f;
    float ys = oy*R, xs = ox*R;
    int y0 = min((int)ys, 46), x0 = min((int)xs, 46);
    float wy = ys - (float)y0, wx = xs - (float)x0;
    const float4* q = (const float4*)(g_q + (size_t)bg*K_SLAB);
    int i00 = (y0*48 + x0)*8 + c4;
    float4 a = q[i00], bb = q[i00+8], c = q[i00+384], d = q[i00+392];
    float w00 = (1.f-wy)*(1.f-wx), w01 = (1.f-wy)*wx, w10 = wy*(1.f-wx), w11 = wy*wx;
    float4 o;
    o.x = a.x*w00 + bb.x*w01 + c.x*w10 + d.x*w11;
    o.y = a.y*w00 + bb.y*w01 + c.y*w10 + d.y*w11;
    o.z = a.z*w00 + bb.z*w01 + c.z*w10 + d.z*w11;
    o.w = a.w*w00 + bb.w*w01 + c.w*w10 + d.w*w11;
    ((float4*)(g_qup + (size_t)bg*QUP_SLAB))[(oy*96+ox)*8 + c4] = o;
}

// ---------------- k4: depthwise 3x3 + channel-LN + exact GeLU -----------------
__global__ void k4_dw(const float* __restrict__ dw_w,
                      const float* __restrict__ offg, const float* __restrict__ offb)
{
    int bid = blockIdx.x;                // 4608: bg*1152 + pixgroup
    int bg = bid / 1152; int p0 = (bid % 1152)*8;
    int w = threadIdx.x >> 5, lane = threadIdx.x & 31;
    int p = p0 + w; int oy = p/96, ox = p%96;
    const float* src = g_qup + (size_t)bg*QUP_SLAB;
    float acc = 0.f;
    #pragma unroll
    for (int ky = 0; ky < 3; ky++) {
        int ny = oy + ky - 1;
        if (ny < 0 || ny > 95) continue;
        #pragma unroll
        for (int kx = 0; kx < 3; kx++) {
            int nx = ox + kx - 1;
            if (nx < 0 || nx > 95) continue;
            acc += src[(ny*96+nx)*32 + lane] * dw_w[lane*9 + ky*3 + kx];
        }
    }
    float s = acc, q = acc*acc;
    #pragma unroll
    for (int o = 16; o; o >>= 1) { s += __shfl_xor_sync(0xffffffffu, s, o); q += __shfl_xor_sync(0xffffffffu, q, o); }
    float mu = s*(1.f/32.f);
    float var = q*(1.f/32.f) - mu*mu;
    float rs = rsqrtf(var + 1e-5f);
    float v = (acc - mu)*rs*offg[lane] + offb[lane];
    float ge = 0.5f*v*(1.f + erff(v*0.70710678118654752f));
    g_t[(size_t)bg*QUP_SLAB + p*32 + lane] = ge;
}

// ---------------- k5: offset conv 3x3 (32->18) + coords -----------------------
__global__ void k5_off(const float* __restrict__ off_b)
{
    __shared__ float st[3*98*33];
    int bid = blockIdx.x;                // 384: bg*96 + oy
    int bg = bid / 96; int oy = bid % 96;
    int t = threadIdx.x;                 // 96
    const float* src = g_t + (size_t)bg*QUP_SLAB;
    for (int i = t; i < 3*98*32; i += 96) {
        int c = i & 31; int rem = i >> 5; int xx = rem % 98 - 1; int dy = rem / 98;
        int ny = oy + dy - 1;
        float v = 0.f;
        if (ny >= 0 && ny < 96 && xx >= 0 && xx < 96) v = src[(ny*96+xx)*32 + c];
        st[(dy*98 + (xx+1))*33 + c] = v;
    }
    __syncthreads();
    int half = t & 1, pxg = t >> 1; int px0 = pxg*2;
    float acc[2][9];
    #pragma unroll
    for (int i = 0; i < 2; i++)
        #pragma unroll
        for (int j = 0; j < 9; j++) acc[i][j] = 0.f;

    for (int c = 0; c < 32; c++) {
        #pragma unroll
        for (int k = 0; k < 9; k++) {
            const float* wp = &g_w2[((half*32 + c)*9 + k)*12];
            float4 wa = *(const float4*)wp;
            float4 wb = *(const float4*)(wp + 4);
            float  w8 = wp[8];
            int dy = k/3, dx = k%3;
            float t0 = st[(dy*98 + px0 + dx)*33 + c];
            float t1 = st[(dy*98 + px0 + 1 + dx)*33 + c];
            acc[0][0] += t0*wa.x; acc[0][1] += t0*wa.y; acc[0][2] += t0*wa.z; acc[0][3] += t0*wa.w;
            acc[0][4] += t0*wb.x; acc[0][5] += t0*wb.y; acc[0][6] += t0*wb.z; acc[0][7] += t0*wb.w;
            acc[0][8] += t0*w8;
            acc[1][0] += t1*wa.x; acc[1][1] += t1*wa.y; acc[1][2] += t1*wa.z; acc[1][3] += t1*wa.w;
            acc[1][4] += t1*wb.x; acc[1][5] += t1*wb.y; acc[1][6] += t1*wb.z; acc[1][7] += t1*wb.w;
            acc[1][8] += t1*w8;
        }
    }
    const float R = 47.0f/95.0f;
    #pragma unroll
    for (int i = 0; i < 2; i++) {
        int ox = px0 + i;
        int p = oy*96 + ox;
        #pragma unroll
        for (int j = 0; j < 9; j++) {
            float pred = acc[i][j] + off_b[j*2 + half];
            float o = tanhf(pred)*11.0f;
            float base = (half == 0) ? (float)(j/3 - 1) : (float)(j%3 - 1);
            float pix  = o + base + (half == 0 ? (float)oy : (float)ox);
            g_crd[(((size_t)bg*NPIX + p)*9 + j)*2 + half] = pix * R;
        }
    }
}

// ---------------- k6: deformable attention ------------------------------------
__global__ void k6_attn(const float* __restrict__ rpb, float* __restrict__ out)
{
    __shared__ float so[16*129];
    int bid = blockIdx.x;                // 2304 blocks * 16 px
    int w = threadIdx.x >> 5, lane = threadIdx.x & 31;
    int pg = bid * 16;
    int bh = pg / NPIX; int b = bh >> 1, h = bh & 1;
    int prel0 = pg % NPIX;
    const float* kbase = g_k  + (size_t)bh*K_SLAB;
    const float* vbase = g_xt + (size_t)bh*XT_SLAB;
    const float* crd0  = g_crd + (size_t)bh*NPIX*18;

    for (int i = 0; i < 2; i++) {
        int prel = prel0 + w*2 + i;
        float qv = g_qup[(size_t)bh*QUP_SLAB + prel*32 + lane] * 0.1767766952966369f;
        const float* cp = crd0 + (size_t)prel*18;
        float a[9];
        float mx = -1e30f;
        #pragma unroll
        for (int j = 0; j < 9; j++) {
            float iy = cp[2*j], ix = cp[2*j+1];
            float y0f = floorf(iy), x0f = floorf(ix);
            float wy = iy - y0f, wx = ix - x0f;
            int y0 = (int)y0f, x0 = (int)x0f;
            bool yi0 = (y0 >= 0) && (y0 < 48);
            bool yi1 = (y0 >= -1) && (y0 < 47);
            bool xi0 = (x0 >= 0) && (x0 < 48);
            bool xi1 = (x0 >= -1) && (x0 < 47);
            float kv = 0.f;
            if (yi0 && xi0) kv += (1.f-wy)*(1.f-wx)*kbase[(y0*48+x0)*32 + lane];
            if (yi0 && xi1) kv += (1.f-wy)*wx      *kbase[(y0*48+x0+1)*32 + lane];
            if (yi1 && xi0) kv += wy*(1.f-wx)      *kbase[((y0+1)*48+x0)*32 + lane];
            if (yi1 && xi1) kv += wy*wx            *kbase[((y0+1)*48+x0+1)*32 + lane];
            kv += rpb[(h*9 + j)*32 + lane];
            float d = qv*kv;
            #pragma unroll
            for (int o = 16; o; o >>= 1) d += __shfl_xor_sync(0xffffffffu, d, o);
            a[j] = d;
            mx = fmaxf(mx, d);
        }
        float ssum = 0.f;
        #pragma unroll
        for (int j = 0; j < 9; j++) { a[j] = expf(a[j] - mx); ssum += a[j]; }
        float inv = 1.f/ssum;
        float4 acc = make_float4(0.f, 0.f, 0.f, 0.f);
        #pragma unroll
        for (int j = 0; j < 9; j++) {
            float iy = cp[2*j], ix = cp[2*j+1];
            float y0f = floorf(iy), x0f = floorf(ix);
            float wy = iy - y0f, wx = ix - x0f;
            int y0 = (int)y0f, x0 = (int)x0f;
            bool yi0 = (y0 >= 0) && (y0 < 48);
            bool yi1 = (y0 >= -1) && (y0 < 47);
            bool xi0 = (x0 >= 0) && (x0 < 48);
            bool xi1 = (x0 >= -1) && (x0 < 47);
            float aw = a[j]*inv;
            if (yi0 && xi0) {
                float4 v = *(const float4*)&vbase[(y0*48+x0)*128 + lane*4];
                float cw = aw*(1.f-wy)*(1.f-wx);
                acc.x += cw*v.x; acc.y += cw*v.y; acc.z += cw*v.z; acc.w += cw*v.w;
            }
            if (yi0 && xi1) {
                float4 v = *(const float4*)&vbase[(y0*48+x0+1)*128 + lane*4];
                float cw = aw*(1.f-wy)*wx;
                acc.x += cw*v.x; acc.y += cw*v.y; acc.z += cw*v.z; acc.w += cw*v.w;
            }
            if (yi1 && xi0) {
                float4 v = *(const float4*)&vbase[((y0+1)*48+x0)*128 + lane*4];
                float cw = aw*wy*(1.f-wx);
                acc.x += cw*v.x; acc.y += cw*v.y; acc.z += cw*v.z; acc.w += cw*v.w;
            }
            if (yi1 && xi1) {
                float4 v = *(const float4*)&vbase[((y0+1)*48+x0+1)*128 + lane*4];
                float cw = aw*wy*wx;
                acc.x += cw*v.x; acc.y += cw*v.y; acc.z += cw*v.z; acc.w += cw*v.w;
            }
        }
        float* sp = &so[(w*2 + i)*129 + lane*4];
        sp[0] = acc.x; sp[1] = acc.y; sp[2] = acc.z; sp[3] = acc.w;
    }
    __syncthreads();
    float* ob = out + ((size_t)(b*256 + h*128))*NPIX + prel0;
    for (int idx = threadIdx.x; idx < 2048; idx += 256) {
        int ch = idx >> 4, px = idx & 15;
        ob[(size_t)ch*NPIX + px] = so[px*129 + ch];
    }
}

extern "C" void kernel_launch(void* const* d_in, const int* in_sizes, int n_in,
                              void* d_out, int out_size)
{
    const float* x       = (const float*)d_in[0];
    const float* ln_g    = (const float*)d_in[1];
    const float* ln_b    = (const float*)d_in[2];
    const float* Wq      = (const float*)d_in[3];
    const float* Wk      = (const float*)d_in[4];
    const float* dw_w    = (const float*)d_in[5];
    const float* off_lng = (const float*)d_in[6];
    const float* off_lnb = (const float*)d_in[7];
    const float* off_w   = (const float*)d_in[8];
    const float* off_b   = (const float*)d_in[9];
    const float* rpb     = (const float*)d_in[10];

    k0_prep<<<1, 256>>>(Wq, Wk, ln_g, ln_b, off_w);
    k1_tr<<<96, 256>>>(x);
    k2_qk<<<192, 96>>>();
    k3_resize<<<(4*NPIX*8)/256, 256>>>();
    k4_dw<<<4608, 256>>>(dw_w, off_lng, off_lnb);
    k5_off<<<384, 96>>>(off_b);
    k6_attn<<<2304, 256>>>(rpb, (float*)d_out);
}

// round 3
// speedup vs baseline: 1.0538x; 1.0538x over previous
#include <cuda_runtime.h>
#include <math.h>

#define HW       2304      // 48*48
#define NPIX     9216      // 96*96
#define XT_SLAB  294912    // 48*48*128
#define K_SLAB   73728     // 48*48*32
#define QUP_SLAB 294912    // 96*96*32

__device__ __align__(128) float g_xt [4*XT_SLAB];   // x channel-last per (b,g)
__device__ __align__(128) float g_k  [4*K_SLAB];    // k channel-last per (b,g)
__device__ __align__(128) float g_q  [4*K_SLAB];    // q lowres channel-last
__device__ __align__(128) float g_qup[4*QUP_SLAB];  // q upsampled channel-last
__device__ __align__(128) float g_t  [4*QUP_SLAB];  // gelu(ln(dwconv(q_up)))
__device__ __align__(128) float g_crd[4*NPIX*18];   // (iy,ix) per (bg,pix,tap)
__device__ float g_mu[2*HW], g_rstd[2*HW];
__device__ __align__(128) float g_WT[256*128];      // [c][o]; o<64: Wq, o>=64: Wk (LN-gain folded)
__device__ float g_csum[128], g_bias2[128];
__device__ __align__(128) float g_w2[2*32*9*12];    // [half][c][tapk][j(pad12)]

// ---------------- k0: fold LN into weights (parallel), transpose offset weights
__global__ void k0_prep(const float* __restrict__ Wq, const float* __restrict__ Wk,
                        const float* __restrict__ g, const float* __restrict__ b,
                        const float* __restrict__ off_w)
{
    if (blockIdx.x >= 128) {
        int i = (blockIdx.x - 128)*256 + threadIdx.x;
        if (i < 2*32*9*12) {
            int j = i % 12; int k = (i/12) % 9; int c = (i/108) % 32; int half = i/3456;
            g_w2[i] = (j < 9) ? off_w[((j*2+half)*32 + c)*9 + k] : 0.f;
        }
        return;
    }
    int o = blockIdx.x, c = threadIdx.x;            // 256 threads, one per input channel
    const float* Wr = (o < 64) ? (Wq + o*256) : (Wk + (o-64)*256);
    float w  = Wr[c];
    float gc = g[c];
    g_WT[c*128 + o] = w*gc;
    float cs = w*gc, bs = w*b[c];
    #pragma unroll
    for (int off = 16; off; off >>= 1) {
        cs += __shfl_xor_sync(0xffffffffu, cs, off);
        bs += __shfl_xor_sync(0xffffffffu, bs, off);
    }
    __shared__ float scs[8], sbs[8];
    int wid = c >> 5, lane = c & 31;
    if (lane == 0) { scs[wid] = cs; sbs[wid] = bs; }
    __syncthreads();
    if (c == 0) {
        float a = 0.f, bbv = 0.f;
        #pragma unroll
        for (int i = 0; i < 8; i++) { a += scs[i]; bbv += sbs[i]; }
        g_csum[o] = a; g_bias2[o] = bbv;
    }
}

// ---------------- k1: transpose x to channel-last + LN stats ------------------
__global__ void k1_tr(const float* __restrict__ x)
{
    __shared__ float xs[128*49];
    __shared__ float ssum[48], ssq[48];
    int b = blockIdx.x / 48, y = blockIdx.x % 48;
    int t = threadIdx.x; // 256
    if (t < 48) { ssum[t] = 0.f; ssq[t] = 0.f; }
    int wid = t >> 5, lane = t & 31;
    for (int half = 0; half < 2; half++) {
        __syncthreads();
        const float* src = x + ((size_t)(b*256 + half*128))*HW + y*48;
        for (int idx = t; idx < 128*48; idx += 256) {
            int c = idx / 48, xx = idx - c*48;
            xs[c*49 + xx] = src[(size_t)c*HW + xx];
        }
        __syncthreads();
        for (int xx = wid; xx < 48; xx += 8) {
            float s = 0.f, q = 0.f;
            #pragma unroll
            for (int j = 0; j < 4; j++) { float v = xs[(lane + 32*j)*49 + xx]; s += v; q += v*v; }
            #pragma unroll
            for (int o = 16; o; o >>= 1) { s += __shfl_xor_sync(0xffffffffu, s, o); q += __shfl_xor_sync(0xffffffffu, q, o); }
            if (lane == 0) { ssum[xx] += s; ssq[xx] += q; }
        }
        float* dst = g_xt + ((size_t)(b*2 + half))*XT_SLAB + (size_t)y*48*128;
        for (int idx = t; idx < 128*48; idx += 256) {
            int xx = idx >> 7, c = idx & 127;
            dst[xx*128 + c] = xs[c*49 + xx];
        }
    }
    __syncthreads();
    if (t < 48) {
        float mu = ssum[t] * (1.0f/256.0f);
        float var = ssq[t] * (1.0f/256.0f) - mu*mu;
        int p = b*HW + y*48 + t;
        g_mu[p] = mu;
        g_rstd[p] = rsqrtf(var + 1e-5f);
    }
}

// ---------------- k2: Q/K projection (1px x 8out per thread) ------------------
__global__ void k2_qk()
{
    int t = threadIdx.x;                 // 256
    int og = t & 15, pg = t >> 4;
    int P = blockIdx.x*16 + pg;          // 0..4607 (b,pixel)
    int b = P / HW, p = P % HW;
    int o0 = og*8;
    const float* x0 = g_xt + (size_t)(b*2)*XT_SLAB + (size_t)p*128;
    float acc[8];
    #pragma unroll
    for (int j = 0; j < 8; j++) acc[j] = 0.f;

    #pragma unroll 4
    for (int c = 0; c < 256; c++) {
        float4 w0 = *(const float4*)&g_WT[c*128 + o0];
        float4 w1 = *(const float4*)&g_WT[c*128 + o0 + 4];
        float xv = x0[((c >> 7) * XT_SLAB) + (c & 127)];
        acc[0] += xv*w0.x; acc[1] += xv*w0.y; acc[2] += xv*w0.z; acc[3] += xv*w0.w;
        acc[4] += xv*w1.x; acc[5] += xv*w1.y; acc[6] += xv*w1.z; acc[7] += xv*w1.w;
    }
    float mu = g_mu[b*HW + p], rs = g_rstd[b*HW + p];
    float4 v0, v1;
    v0.x = rs*(acc[0] - mu*g_csum[o0+0]) + g_bias2[o0+0];
    v0.y = rs*(acc[1] - mu*g_csum[o0+1]) + g_bias2[o0+1];
    v0.z = rs*(acc[2] - mu*g_csum[o0+2]) + g_bias2[o0+2];
    v0.w = rs*(acc[3] - mu*g_csum[o0+3]) + g_bias2[o0+3];
    v1.x = rs*(acc[4] - mu*g_csum[o0+4]) + g_bias2[o0+4];
    v1.y = rs*(acc[5] - mu*g_csum[o0+5]) + g_bias2[o0+5];
    v1.z = rs*(acc[6] - mu*g_csum[o0+6]) + g_bias2[o0+6];
    v1.w = rs*(acc[7] - mu*g_csum[o0+7]) + g_bias2[o0+7];
    int isK = (o0 >= 64);
    int oo  = o0 & 63;
    int grp = oo >> 5, cl0 = oo & 31;
    float* dst = (isK ? g_k : g_q) + (size_t)(b*2 + grp)*K_SLAB + (size_t)p*32;
    *(float4*)&dst[cl0]     = v0;
    *(float4*)&dst[cl0 + 4] = v1;
}

// ---------------- k3: bilinear resize q 48 -> 96 (align_corners) --------------
__global__ void k3_resize()
{
    int idx = blockIdx.x*256 + threadIdx.x;   // 4*9216*8
    int c4 = idx & 7; int r = idx >> 3;
    int ox = r % 96; r /= 96; int oy = r % 96; int bg = r / 96;
    const float R = 47.0f/95.0f;
    float ys = oy*R, xs = ox*R;
    int y0 = min((int)ys, 46), x0 = min((int)xs, 46);
    float wy = ys - (float)y0, wx = xs - (float)x0;
    const float4* q = (const float4*)(g_q + (size_t)bg*K_SLAB);
    int i00 = (y0*48 + x0)*8 + c4;
    float4 a = q[i00], bb = q[i00+8], c = q[i00+384], d = q[i00+392];
    float w00 = (1.f-wy)*(1.f-wx), w01 = (1.f-wy)*wx, w10 = wy*(1.f-wx), w11 = wy*wx;
    float4 o;
    o.x = a.x*w00 + bb.x*w01 + c.x*w10 + d.x*w11;
    o.y = a.y*w00 + bb.y*w01 + c.y*w10 + d.y*w11;
    o.z = a.z*w00 + bb.z*w01 + c.z*w10 + d.z*w11;
    o.w = a.w*w00 + bb.w*w01 + c.w*w10 + d.w*w11;
    ((float4*)(g_qup + (size_t)bg*QUP_SLAB))[(oy*96+ox)*8 + c4] = o;
}

// ---------------- k4: depthwise 3x3 + channel-LN + exact GeLU (smem tile) -----
__global__ void k4_dw(const float* __restrict__ dw_w,
                      const float* __restrict__ offg, const float* __restrict__ offb)
{
    __shared__ float sq[3*34*32];        // 13 KB
    int bid = blockIdx.x;                // 1152: bg*288 + oy*3 + xc
    int bg = bid / 288; int rem = bid % 288; int oy = rem / 3; int xc = rem % 3;
    int xbase = xc*32;
    const float* src = g_qup + (size_t)bg*QUP_SLAB;
    int t = threadIdx.x;                 // 256
    for (int i = t; i < 3*34*32; i += 256) {
        int c = i & 31; int r = i >> 5; int xx = r % 34 - 1 + xbase; int dy = r / 34;
        int ny = oy + dy - 1;
        float v = 0.f;
        if (ny >= 0 && ny < 96 && xx >= 0 && xx < 96) v = src[(ny*96+xx)*32 + c];
        sq[i] = v;
    }
    __syncthreads();
    int w = t >> 5, lane = t & 31;
    float wreg[9];
    #pragma unroll
    for (int k = 0; k < 9; k++) wreg[k] = dw_w[lane*9 + k];
    float lg = offg[lane], lb = offb[lane];
    #pragma unroll
    for (int pp = 0; pp < 4; pp++) {
        int lx = w*4 + pp;               // 0..31 local x
        float acc = 0.f;
        #pragma unroll
        for (int ky = 0; ky < 3; ky++)
            #pragma unroll
            for (int kx = 0; kx < 3; kx++)
                acc += sq[(ky*34 + lx + kx)*32 + lane] * wreg[ky*3+kx];
        float s = acc, q = acc*acc;
        #pragma unroll
        for (int o = 16; o; o >>= 1) { s += __shfl_xor_sync(0xffffffffu, s, o); q += __shfl_xor_sync(0xffffffffu, q, o); }
        float mu = s*(1.f/32.f);
        float var = q*(1.f/32.f) - mu*mu;
        float rs = rsqrtf(var + 1e-5f);
        float v = (acc - mu)*rs*lg + lb;
        float ge = 0.5f*v*(1.f + erff(v*0.70710678118654752f));
        g_t[(size_t)bg*QUP_SLAB + (oy*96 + xbase + lx)*32 + lane] = ge;
    }
}

// ---------------- k5: offset conv 3x3 (32->18) + coords (1px x 9out) ----------
__global__ void k5_off(const float* __restrict__ off_b)
{
    __shared__ float st[3*98*33];        // 38.8 KB
    int bid = blockIdx.x;                // 384: bg*96 + oy
    int bg = bid / 96; int oy = bid % 96;
    int t = threadIdx.x;                 // 192
    const float* src = g_t + (size_t)bg*QUP_SLAB;
    for (int i = t; i < 3*98*32; i += 192) {
        int c = i & 31; int rem = i >> 5; int xx = rem % 98 - 1; int dy = rem / 98;
        int ny = oy + dy - 1;
        float v = 0.f;
        if (ny >= 0 && ny < 96 && xx >= 0 && xx < 96) v = src[(ny*96+xx)*32 + c];
        st[(dy*98 + (xx+1))*33 + c] = v;
    }
    __syncthreads();
    int px = t >> 1, half = t & 1;
    float acc[9];
    #pragma unroll
    for (int j = 0; j < 9; j++) acc[j] = 0.f;

    for (int c = 0; c < 32; c++) {
        float tv[9];
        #pragma unroll
        for (int k = 0; k < 9; k++)
            tv[k] = st[((k/3)*98 + px + (k%3))*33 + c];
        #pragma unroll
        for (int k = 0; k < 9; k++) {
            const float* wp = &g_w2[((half*32 + c)*9 + k)*12];
            float4 wa = *(const float4*)wp;
            float4 wb = *(const float4*)(wp + 4);
            float  w8 = wp[8];
            acc[0] += tv[k]*wa.x; acc[1] += tv[k]*wa.y; acc[2] += tv[k]*wa.z; acc[3] += tv[k]*wa.w;
            acc[4] += tv[k]*wb.x; acc[5] += tv[k]*wb.y; acc[6] += tv[k]*wb.z; acc[7] += tv[k]*wb.w;
            acc[8] += tv[k]*w8;
        }
    }
    const float R = 47.0f/95.0f;
    int p = oy*96 + px;
    #pragma unroll
    for (int j = 0; j < 9; j++) {
        float pred = acc[j] + off_b[j*2 + half];
        float o = tanhf(pred)*11.0f;
        float base = (half == 0) ? (float)(j/3 - 1) : (float)(j%3 - 1);
        float pix  = o + base + (half == 0 ? (float)oy : (float)px);
        g_crd[(((size_t)bg*NPIX + p)*9 + j)*2 + half] = pix * R;
    }
}

// ---------------- k6: deformable attention ------------------------------------
__global__ void k6_attn(const float* __restrict__ rpb, float* __restrict__ out)
{
    __shared__ float so[16*129];
    int bid = blockIdx.x;                // 2304 blocks * 16 px
    int w = threadIdx.x >> 5, lane = threadIdx.x & 31;
    int pg = bid * 16;
    int bh = pg / NPIX; int b = bh >> 1, h = bh & 1;
    int prel0 = pg % NPIX;
    const float* kbase = g_k  + (size_t)bh*K_SLAB;
    const float* vbase = g_xt + (size_t)bh*XT_SLAB;
    const float* crd0  = g_crd + (size_t)bh*NPIX*18;
    float rp[9];
    #pragma unroll
    for (int j = 0; j < 9; j++) rp[j] = rpb[(h*9 + j)*32 + lane];

    for (int i = 0; i < 2; i++) {
        int prel = prel0 + w*2 + i;
        float qv = g_qup[(size_t)bh*QUP_SLAB + prel*32 + lane] * 0.1767766952966369f;
        const float* cp = crd0 + (size_t)prel*18;
        int   y0a[9], x0a[9];
        float wya[9], wxa[9];
        float a[9];
        float mx = -1e30f;
        #pragma unroll
        for (int j = 0; j < 9; j++) {
            float iy = cp[2*j], ix = cp[2*j+1];
            float y0f = floorf(iy), x0f = floorf(ix);
            float wy = iy - y0f, wx = ix - x0f;
            int y0 = (int)y0f, x0 = (int)x0f;
            y0a[j] = y0; x0a[j] = x0; wya[j] = wy; wxa[j] = wx;
            bool yi0 = (y0 >= 0) && (y0 < 48);
            bool yi1 = (y0 >= -1) && (y0 < 47);
            bool xi0 = (x0 >= 0) && (x0 < 48);
            bool xi1 = (x0 >= -1) && (x0 < 47);
            float kv = 0.f;
            if (yi0 && xi0) kv += (1.f-wy)*(1.f-wx)*kbase[(y0*48+x0)*32 + lane];
            if (yi0 && xi1) kv += (1.f-wy)*wx      *kbase[(y0*48+x0+1)*32 + lane];
            if (yi1 && xi0) kv += wy*(1.f-wx)      *kbase[((y0+1)*48+x0)*32 + lane];
            if (yi1 && xi1) kv += wy*wx            *kbase[((y0+1)*48+x0+1)*32 + lane];
            kv += rp[j];
            float d = qv*kv;
            #pragma unroll
            for (int o = 16; o; o >>= 1) d += __shfl_xor_sync(0xffffffffu, d, o);
            a[j] = d;
            mx = fmaxf(mx, d);
        }
        float ssum = 0.f;
        #pragma unroll
        for (int j = 0; j < 9; j++) { a[j] = __expf(a[j] - mx); ssum += a[j]; }
        float inv = __fdividef(1.f, ssum);
        float4 acc = make_float4(0.f, 0.f, 0.f, 0.f);
        #pragma unroll
        for (int j = 0; j < 9; j++) {
            int y0 = y0a[j], x0 = x0a[j];
            float wy = wya[j], wx = wxa[j];
            bool yi0 = (y0 >= 0) && (y0 < 48);
            bool yi1 = (y0 >= -1) && (y0 < 47);
            bool xi0 = (x0 >= 0) && (x0 < 48);
            bool xi1 = (x0 >= -1) && (x0 < 47);
            float aw = a[j]*inv;
            if (yi0 && xi0) {
                float4 v = *(const float4*)&vbase[(y0*48+x0)*128 + lane*4];
                float cw = aw*(1.f-wy)*(1.f-wx);
                acc.x += cw*v.x; acc.y += cw*v.y; acc.z += cw*v.z; acc.w += cw*v.w;
            }
            if (yi0 && xi1) {
                float4 v = *(const float4*)&vbase[(y0*48+x0+1)*128 + lane*4];
                float cw = aw*(1.f-wy)*wx;
                acc.x += cw*v.x; acc.y += cw*v.y; acc.z += cw*v.z; acc.w += cw*v.w;
            }
            if (yi1 && xi0) {
                float4 v = *(const float4*)&vbase[((y0+1)*48+x0)*128 + lane*4];
                float cw = aw*wy*(1.f-wx);
                acc.x += cw*v.x; acc.y += cw*v.y; acc.z += cw*v.z; acc.w += cw*v.w;
            }
            if (yi1 && xi1) {
                float4 v = *(const float4*)&vbase[((y0+1)*48+x0+1)*128 + lane*4];
                float cw = aw*wy*wx;
                acc.x += cw*v.x; acc.y += cw*v.y; acc.z += cw*v.z; acc.w += cw*v.w;
            }
        }
        float* sp = &so[(w*2 + i)*129 + lane*4];
        sp[0] = acc.x; sp[1] = acc.y; sp[2] = acc.z; sp[3] = acc.w;
    }
    __syncthreads();
    float* ob = out + ((size_t)(b*256 + h*128))*NPIX + prel0;
    for (int idx = threadIdx.x; idx < 2048; idx += 256) {
        int ch = idx >> 4, px = idx & 15;
        ob[(size_t)ch*NPIX + px] = so[px*129 + ch];
    }
}

extern "C" void kernel_launch(void* const* d_in, const int* in_sizes, int n_in,
                              void* d_out, int out_size)
{
    const float* x       = (const float*)d_in[0];
    const float* ln_g    = (const float*)d_in[1];
    const float* ln_b    = (const float*)d_in[2];
    const float* Wq      = (const float*)d_in[3];
    const float* Wk      = (const float*)d_in[4];
    const float* dw_w    = (const float*)d_in[5];
    const float* off_lng = (const float*)d_in[6];
    const float* off_lnb = (const float*)d_in[7];
    const float* off_w   = (const float*)d_in[8];
    const float* off_b   = (const float*)d_in[9];
    const float* rpb     = (const float*)d_in[10];

    k0_prep<<<155, 256>>>(Wq, Wk, ln_g, ln_b, off_w);
    k1_tr<<<96, 256>>>(x);
    k2_qk<<<288, 256>>>();
    k3_resize<<<(4*NPIX*8)/256, 256>>>();
    k4_dw<<<1152, 256>>>(dw_w, off_lng, off_lnb);
    k5_off<<<384, 192>>>(off_b);
    k6_attn<<<2304, 256>>>(rpb, (float*)d_out);
}

// round 4
// speedup vs baseline: 1.5303x; 1.4522x over previous
#include <cuda_runtime.h>
#include <math.h>

#define HW       2304      // 48*48
#define NPIX     9216      // 96*96
#define XT_SLAB  294912    // 48*48*128
#define K_SLAB   73728     // 48*48*32

__device__ __align__(128) float g_xt [4*XT_SLAB];   // x channel-last per (b,g)
__device__ __align__(128) float g_k  [4*K_SLAB];    // k channel-last per (b,g)
__device__ __align__(128) float g_q  [4*K_SLAB];    // q lowres channel-last
__device__ __align__(128) float g_t  [4*NPIX*32];   // gelu(ln(dwconv(resize(q))))
__device__ __align__(128) float g_crd[4*NPIX*18];   // (iy,ix) per (bg,pix,tap)
__device__ float g_mu[2*HW], g_rstd[2*HW];
__device__ __align__(128) float g_WT[256*128];      // [c][o]; o<64: Wq, o>=64: Wk (LN-gain folded)
__device__ float g_csum[128], g_bias2[128];
__device__ __align__(128) float g_w2[2*32*9*12];    // [half][c][tapk][j(pad12)]

// ---------------- k0: fold LN into weights (parallel), transpose offset weights
__global__ void k0_prep(const float* __restrict__ Wq, const float* __restrict__ Wk,
                        const float* __restrict__ g, const float* __restrict__ b,
                        const float* __restrict__ off_w)
{
    if (blockIdx.x >= 128) {
        int i = (blockIdx.x - 128)*256 + threadIdx.x;
        if (i < 2*32*9*12) {
            int j = i % 12; int k = (i/12) % 9; int c = (i/108) % 32; int half = i/3456;
            g_w2[i] = (j < 9) ? off_w[((j*2+half)*32 + c)*9 + k] : 0.f;
        }
        return;
    }
    int o = blockIdx.x, c = threadIdx.x;            // 256 threads, one per input channel
    const float* Wr = (o < 64) ? (Wq + o*256) : (Wk + (o-64)*256);
    float w  = Wr[c];
    float gc = g[c];
    g_WT[c*128 + o] = w*gc;
    float cs = w*gc, bs = w*b[c];
    #pragma unroll
    for (int off = 16; off; off >>= 1) {
        cs += __shfl_xor_sync(0xffffffffu, cs, off);
        bs += __shfl_xor_sync(0xffffffffu, bs, off);
    }
    __shared__ float scs[8], sbs[8];
    int wid = c >> 5, lane = c & 31;
    if (lane == 0) { scs[wid] = cs; sbs[wid] = bs; }
    __syncthreads();
    if (c == 0) {
        float a = 0.f, bbv = 0.f;
        #pragma unroll
        for (int i = 0; i < 8; i++) { a += scs[i]; bbv += sbs[i]; }
        g_csum[o] = a; g_bias2[o] = bbv;
    }
}

// ---------------- k1: transpose x to channel-last + LN stats ------------------
__global__ void k1_tr(const float* __restrict__ x)
{
    __shared__ float xs[128*49];
    __shared__ float ssum[48], ssq[48];
    int b = blockIdx.x / 48, y = blockIdx.x % 48;
    int t = threadIdx.x; // 256
    if (t < 48) { ssum[t] = 0.f; ssq[t] = 0.f; }
    int wid = t >> 5, lane = t & 31;
    for (int half = 0; half < 2; half++) {
        __syncthreads();
        const float* src = x + ((size_t)(b*256 + half*128))*HW + y*48;
        for (int idx = t; idx < 128*48; idx += 256) {
            int c = idx / 48, xx = idx - c*48;
            xs[c*49 + xx] = src[(size_t)c*HW + xx];
        }
        __syncthreads();
        for (int xx = wid; xx < 48; xx += 8) {
            float s = 0.f, q = 0.f;
            #pragma unroll
            for (int j = 0; j < 4; j++) { float v = xs[(lane + 32*j)*49 + xx]; s += v; q += v*v; }
            #pragma unroll
            for (int o = 16; o; o >>= 1) { s += __shfl_xor_sync(0xffffffffu, s, o); q += __shfl_xor_sync(0xffffffffu, q, o); }
            if (lane == 0) { ssum[xx] += s; ssq[xx] += q; }
        }
        float* dst = g_xt + ((size_t)(b*2 + half))*XT_SLAB + (size_t)y*48*128;
        for (int idx = t; idx < 128*48; idx += 256) {
            int xx = idx >> 7, c = idx & 127;
            dst[xx*128 + c] = xs[c*49 + xx];
        }
    }
    __syncthreads();
    if (t < 48) {
        float mu = ssum[t] * (1.0f/256.0f);
        float var = ssq[t] * (1.0f/256.0f) - mu*mu;
        int p = b*HW + y*48 + t;
        g_mu[p] = mu;
        g_rstd[p] = rsqrtf(var + 1e-5f);
    }
}

// ---------------- k2: Q/K projection (1px x 8out, float4 x loads) -------------
__global__ void k2_qk()
{
    int t = threadIdx.x;                 // 256
    int og = t & 15, pg = t >> 4;
    int P = blockIdx.x*16 + pg;          // 0..4607 (b,pixel)
    int b = P / HW, p = P % HW;
    int o0 = og*8;
    const float* x0 = g_xt + (size_t)(b*2)*XT_SLAB + (size_t)p*128;
    float acc[8];
    #pragma unroll
    for (int j = 0; j < 8; j++) acc[j] = 0.f;

    for (int h2 = 0; h2 < 2; h2++) {
        const float4* xp = (const float4*)(x0 + (size_t)h2*XT_SLAB);
        #pragma unroll 4
        for (int c4 = 0; c4 < 32; c4++) {
            float4 xv = xp[c4];
            const float* wb = &g_WT[(h2*128 + c4*4)*128 + o0];
            float4 w0, w1;
            w0 = *(const float4*)&wb[0];     w1 = *(const float4*)&wb[4];
            acc[0] += xv.x*w0.x; acc[1] += xv.x*w0.y; acc[2] += xv.x*w0.z; acc[3] += xv.x*w0.w;
            acc[4] += xv.x*w1.x; acc[5] += xv.x*w1.y; acc[6] += xv.x*w1.z; acc[7] += xv.x*w1.w;
            w0 = *(const float4*)&wb[128];   w1 = *(const float4*)&wb[132];
            acc[0] += xv.y*w0.x; acc[1] += xv.y*w0.y; acc[2] += xv.y*w0.z; acc[3] += xv.y*w0.w;
            acc[4] += xv.y*w1.x; acc[5] += xv.y*w1.y; acc[6] += xv.y*w1.z; acc[7] += xv.y*w1.w;
            w0 = *(const float4*)&wb[256];   w1 = *(const float4*)&wb[260];
            acc[0] += xv.z*w0.x; acc[1] += xv.z*w0.y; acc[2] += xv.z*w0.z; acc[3] += xv.z*w0.w;
            acc[4] += xv.z*w1.x; acc[5] += xv.z*w1.y; acc[6] += xv.z*w1.z; acc[7] += xv.z*w1.w;
            w0 = *(const float4*)&wb[384];   w1 = *(const float4*)&wb[388];
            acc[0] += xv.w*w0.x; acc[1] += xv.w*w0.y; acc[2] += xv.w*w0.z; acc[3] += xv.w*w0.w;
            acc[4] += xv.w*w1.x; acc[5] += xv.w*w1.y; acc[6] += xv.w*w1.z; acc[7] += xv.w*w1.w;
        }
    }
    float mu = g_mu[b*HW + p], rs = g_rstd[b*HW + p];
    float4 v0, v1;
    v0.x = rs*(acc[0] - mu*g_csum[o0+0]) + g_bias2[o0+0];
    v0.y = rs*(acc[1] - mu*g_csum[o0+1]) + g_bias2[o0+1];
    v0.z = rs*(acc[2] - mu*g_csum[o0+2]) + g_bias2[o0+2];
    v0.w = rs*(acc[3] - mu*g_csum[o0+3]) + g_bias2[o0+3];
    v1.x = rs*(acc[4] - mu*g_csum[o0+4]) + g_bias2[o0+4];
    v1.y = rs*(acc[5] - mu*g_csum[o0+5]) + g_bias2[o0+5];
    v1.z = rs*(acc[6] - mu*g_csum[o0+6]) + g_bias2[o0+6];
    v1.w = rs*(acc[7] - mu*g_csum[o0+7]) + g_bias2[o0+7];
    int isK = (o0 >= 64);
    int oo  = o0 & 63;
    int grp = oo >> 5, cl0 = oo & 31;
    float* dst = (isK ? g_k : g_q) + (size_t)(b*2 + grp)*K_SLAB + (size_t)p*32;
    *(float4*)&dst[cl0]     = v0;
    *(float4*)&dst[cl0 + 4] = v1;
}

// ---------------- k4: inline resize + depthwise 3x3 + channel-LN + GeLU -------
__global__ void k4_dw(const float* __restrict__ dw_w,
                      const float* __restrict__ offg, const float* __restrict__ offb)
{
    __shared__ float sq[3*34*32];        // 13 KB
    int bid = blockIdx.x;                // 1152: bg*288 + oy*3 + xc
    int bg = bid / 288; int rem = bid % 288; int oy = rem / 3; int xc = rem % 3;
    int xbase = xc*32;
    const float* qb = g_q + (size_t)bg*K_SLAB;
    int t = threadIdx.x;                 // 256
    const float R = 47.0f/95.0f;
    for (int i = t; i < 3*34*32; i += 256) {
        int c = i & 31; int r = i >> 5; int xx = r % 34 - 1 + xbase; int dy = r / 34;
        int ny = oy + dy - 1;
        float v = 0.f;
        if (ny >= 0 && ny < 96 && xx >= 0 && xx < 96) {
            float ys = ny*R, xs = xx*R;
            int y0 = min((int)ys, 46), x0 = min((int)xs, 46);
            float wy = ys - (float)y0, wx = xs - (float)x0;
            int b00 = (y0*48 + x0)*32 + c;
            float qa = qb[b00], qbv = qb[b00+32], qc = qb[b00+1536], qd = qb[b00+1568];
            v = qa*(1.f-wy)*(1.f-wx) + qbv*(1.f-wy)*wx + qc*wy*(1.f-wx) + qd*wy*wx;
        }
        sq[i] = v;
    }
    __syncthreads();
    int w = t >> 5, lane = t & 31;
    float wreg[9];
    #pragma unroll
    for (int k = 0; k < 9; k++) wreg[k] = dw_w[lane*9 + k];
    float lg = offg[lane], lb = offb[lane];
    #pragma unroll
    for (int pp = 0; pp < 4; pp++) {
        int lx = w*4 + pp;               // 0..31 local x
        float acc = 0.f;
        #pragma unroll
        for (int ky = 0; ky < 3; ky++)
            #pragma unroll
            for (int kx = 0; kx < 3; kx++)
                acc += sq[(ky*34 + lx + kx)*32 + lane] * wreg[ky*3+kx];
        float s = acc, q = acc*acc;
        #pragma unroll
        for (int o = 16; o; o >>= 1) { s += __shfl_xor_sync(0xffffffffu, s, o); q += __shfl_xor_sync(0xffffffffu, q, o); }
        float mu = s*(1.f/32.f);
        float var = q*(1.f/32.f) - mu*mu;
        float rs = rsqrtf(var + 1e-5f);
        float v = (acc - mu)*rs*lg + lb;
        float ge = 0.5f*v*(1.f + erff(v*0.70710678118654752f));
        g_t[(size_t)bg*NPIX*32 + (oy*96 + xbase + lx)*32 + lane] = ge;
    }
}

// ---------------- k5: offset conv 3x3 (32->18) + coords (1px x 9out) ----------
__global__ void k5_off(const float* __restrict__ off_b)
{
    __shared__ float st[3*98*33];        // 38.8 KB
    int bid = blockIdx.x;                // 384: bg*96 + oy
    int bg = bid / 96; int oy = bid % 96;
    int t = threadIdx.x;                 // 192
    const float* src = g_t + (size_t)bg*NPIX*32;
    for (int i = t; i < 3*98*32; i += 192) {
        int c = i & 31; int rem = i >> 5; int xx = rem % 98 - 1; int dy = rem / 98;
        int ny = oy + dy - 1;
        float v = 0.f;
        if (ny >= 0 && ny < 96 && xx >= 0 && xx < 96) v = src[(ny*96+xx)*32 + c];
        st[(dy*98 + (xx+1))*33 + c] = v;
    }
    __syncthreads();
    int px = t >> 1, half = t & 1;
    float acc[9];
    #pragma unroll
    for (int j = 0; j < 9; j++) acc[j] = 0.f;

    for (int c = 0; c < 32; c++) {
        float tv[9];
        #pragma unroll
        for (int k = 0; k < 9; k++)
            tv[k] = st[((k/3)*98 + px + (k%3))*33 + c];
        #pragma unroll
        for (int k = 0; k < 9; k++) {
            const float* wp = &g_w2[((half*32 + c)*9 + k)*12];
            float4 wa = *(const float4*)wp;
            float4 wb = *(const float4*)(wp + 4);
            float  w8 = wp[8];
            acc[0] += tv[k]*wa.x; acc[1] += tv[k]*wa.y; acc[2] += tv[k]*wa.z; acc[3] += tv[k]*wa.w;
            acc[4] += tv[k]*wb.x; acc[5] += tv[k]*wb.y; acc[6] += tv[k]*wb.z; acc[7] += tv[k]*wb.w;
            acc[8] += tv[k]*w8;
        }
    }
    const float R = 47.0f/95.0f;
    int p = oy*96 + px;
    #pragma unroll
    for (int j = 0; j < 9; j++) {
        float pred = acc[j] + off_b[j*2 + half];
        float o = tanhf(pred)*11.0f;
        float base = (half == 0) ? (float)(j/3 - 1) : (float)(j%3 - 1);
        float pix  = o + base + (half == 0 ? (float)oy : (float)px);
        g_crd[(((size_t)bg*NPIX + p)*9 + j)*2 + half] = pix * R;
    }
}

// ---------------- k6: deformable attention (4 px/warp, 8 lanes/px) ------------
__global__ void k6_attn(const float* __restrict__ rpb, float* __restrict__ out)
{
    __shared__ float so[128*33];         // [ch][px], 16.9 KB
    int bid = blockIdx.x;                // 1152 blocks * 32 px
    int w = threadIdx.x >> 5, lane = threadIdx.x & 31;
    int sub = lane >> 3, ll = lane & 7;
    int bh = bid / 288; int b = bh >> 1, h = bh & 1;
    int prel0 = (bid % 288) * 32;
    int prel = prel0 + w*4 + sub;
    const float* kbase = g_k  + (size_t)bh*K_SLAB;
    const float* vbase = g_xt + (size_t)bh*XT_SLAB;
    const float* cp = g_crd + (size_t)bh*NPIX*18 + (size_t)prel*18;

    // inline q resize for this pixel (8 lanes x float4 = 32 ch)
    const float R = 47.0f/95.0f;
    int oy = prel / 96, ox = prel % 96;
    float ys = oy*R, xs = ox*R;
    int yq = min((int)ys, 46), xq = min((int)xs, 46);
    float wyq = ys - (float)yq, wxq = xs - (float)xq;
    const float* qb = g_q + (size_t)bh*K_SLAB;
    int q00 = (yq*48 + xq)*32 + ll*4;
    float4 qa = *(const float4*)&qb[q00];
    float4 qb2 = *(const float4*)&qb[q00+32];
    float4 qc = *(const float4*)&qb[q00+1536];
    float4 qd = *(const float4*)&qb[q00+1568];
    float a00 = (1.f-wyq)*(1.f-wxq), a01 = (1.f-wyq)*wxq, a10 = wyq*(1.f-wxq), a11 = wyq*wxq;
    const float S = 0.1767766952966369f;
    float4 qv;
    qv.x = (qa.x*a00 + qb2.x*a01 + qc.x*a10 + qd.x*a11)*S;
    qv.y = (qa.y*a00 + qb2.y*a01 + qc.y*a10 + qd.y*a11)*S;
    qv.z = (qa.z*a00 + qb2.z*a01 + qc.z*a10 + qd.z*a11)*S;
    qv.w = (qa.w*a00 + qb2.w*a01 + qc.w*a10 + qd.w*a11)*S;

    float a[9];
    float mx = -1e30f;
    #pragma unroll
    for (int j = 0; j < 9; j++) {
        float iy = cp[2*j], ix = cp[2*j+1];
        float y0f = floorf(iy), x0f = floorf(ix);
        float wy = iy - y0f, wx = ix - x0f;
        int y0 = (int)y0f, x0 = (int)x0f;
        bool yi0 = (y0 >= 0) & (y0 < 48);
        bool yi1 = (y0 >= -1) & (y0 < 47);
        bool xi0 = (x0 >= 0) & (x0 < 48);
        bool xi1 = (x0 >= -1) & (x0 < 47);
        float w00 = (yi0 & xi0) ? (1.f-wy)*(1.f-wx) : 0.f;
        float w01 = (yi0 & xi1) ? (1.f-wy)*wx : 0.f;
        float w10 = (yi1 & xi0) ? wy*(1.f-wx) : 0.f;
        float w11 = (yi1 & xi1) ? wy*wx : 0.f;
        int yc0 = max(min(y0, 47), 0), yc1 = max(min(y0+1, 47), 0);
        int xc0 = max(min(x0, 47), 0), xc1 = max(min(x0+1, 47), 0);
        float4 c00 = *(const float4*)&kbase[(yc0*48+xc0)*32 + ll*4];
        float4 c01 = *(const float4*)&kbase[(yc0*48+xc1)*32 + ll*4];
        float4 c10 = *(const float4*)&kbase[(yc1*48+xc0)*32 + ll*4];
        float4 c11 = *(const float4*)&kbase[(yc1*48+xc1)*32 + ll*4];
        float4 rv = *(const float4*)&rpb[(h*9 + j)*32 + ll*4];
        float kx0 = c00.x*w00 + c01.x*w01 + c10.x*w10 + c11.x*w11 + rv.x;
        float kx1 = c00.y*w00 + c01.y*w01 + c10.y*w10 + c11.y*w11 + rv.y;
        float kx2 = c00.z*w00 + c01.z*w01 + c10.z*w10 + c11.z*w11 + rv.z;
        float kx3 = c00.w*w00 + c01.w*w01 + c10.w*w10 + c11.w*w11 + rv.w;
        float d = qv.x*kx0 + qv.y*kx1 + qv.z*kx2 + qv.w*kx3;
        d += __shfl_xor_sync(0xffffffffu, d, 4);
        d += __shfl_xor_sync(0xffffffffu, d, 2);
        d += __shfl_xor_sync(0xffffffffu, d, 1);
        a[j] = d;
        mx = fmaxf(mx, d);
    }
    float ssum = 0.f;
    #pragma unroll
    for (int j = 0; j < 9; j++) { a[j] = __expf(a[j] - mx); ssum += a[j]; }
    float inv = __fdividef(1.f, ssum);

    float4 acc[4];
    #pragma unroll
    for (int p2 = 0; p2 < 4; p2++) acc[p2] = make_float4(0.f, 0.f, 0.f, 0.f);

    #pragma unroll
    for (int j = 0; j < 9; j++) {
        float iy = cp[2*j], ix = cp[2*j+1];
        float y0f = floorf(iy), x0f = floorf(ix);
        float wy = iy - y0f, wx = ix - x0f;
        int y0 = (int)y0f, x0 = (int)x0f;
        bool yi0 = (y0 >= 0) & (y0 < 48);
        bool yi1 = (y0 >= -1) & (y0 < 47);
        bool xi0 = (x0 >= 0) & (x0 < 48);
        bool xi1 = (x0 >= -1) & (x0 < 47);
        float aw = a[j]*inv;
        float w00 = (yi0 & xi0) ? aw*(1.f-wy)*(1.f-wx) : 0.f;
        float w01 = (yi0 & xi1) ? aw*(1.f-wy)*wx : 0.f;
        float w10 = (yi1 & xi0) ? aw*wy*(1.f-wx) : 0.f;
        float w11 = (yi1 & xi1) ? aw*wy*wx : 0.f;
        int yc0 = max(min(y0, 47), 0), yc1 = max(min(y0+1, 47), 0);
        int xc0 = max(min(x0, 47), 0), xc1 = max(min(x0+1, 47), 0);
        int r00 = (yc0*48+xc0)*128 + ll*4;
        int r01 = (yc0*48+xc1)*128 + ll*4;
        int r10 = (yc1*48+xc0)*128 + ll*4;
        int r11 = (yc1*48+xc1)*128 + ll*4;
        #pragma unroll
        for (int p2 = 0; p2 < 4; p2++) {
            float4 v00 = *(const float4*)&vbase[r00 + p2*32];
            float4 v01 = *(const float4*)&vbase[r01 + p2*32];
            float4 v10 = *(const float4*)&vbase[r10 + p2*32];
            float4 v11 = *(const float4*)&vbase[r11 + p2*32];
            acc[p2].x += w00*v00.x + w01*v01.x + w10*v10.x + w11*v11.x;
            acc[p2].y += w00*v00.y + w01*v01.y + w10*v10.y + w11*v11.y;
            acc[p2].z += w00*v00.z + w01*v01.z + w10*v10.z + w11*v11.z;
            acc[p2].w += w00*v00.w + w01*v01.w + w10*v10.w + w11*v11.w;
        }
    }
    // store to smem [ch][px] (conflict-free scalar STS)
    int pxl = w*4 + sub;
    #pragma unroll
    for (int p2 = 0; p2 < 4; p2++) {
        int ch = p2*32 + ll*4;
        so[(ch+0)*33 + pxl] = acc[p2].x;
        so[(ch+1)*33 + pxl] = acc[p2].y;
        so[(ch+2)*33 + pxl] = acc[p2].z;
        so[(ch+3)*33 + pxl] = acc[p2].w;
    }
    __syncthreads();
    float* ob = out + ((size_t)(b*256 + h*128))*NPIX + prel0;
    for (int idx = threadIdx.x; idx < 4096; idx += 256) {
        int ch = idx >> 5, px = idx & 31;
        ob[(size_t)ch*NPIX + px] = so[ch*33 + px];
    }
}

extern "C" void kernel_launch(void* const* d_in, const int* in_sizes, int n_in,
                              void* d_out, int out_size)
{
    const float* x       = (const float*)d_in[0];
    const float* ln_g    = (const float*)d_in[1];
    const float* ln_b    = (const float*)d_in[2];
    const float* Wq      = (const float*)d_in[3];
    const float* Wk      = (const float*)d_in[4];
    const float* dw_w    = (const float*)d_in[5];
    const float* off_lng = (const float*)d_in[6];
    const float* off_lnb = (const float*)d_in[7];
    const float* off_w   = (const float*)d_in[8];
    const float* off_b   = (const float*)d_in[9];
    const float* rpb     = (const float*)d_in[10];

    k0_prep<<<155, 256>>>(Wq, Wk, ln_g, ln_b, off_w);
    k1_tr<<<96, 256>>>(x);
    k2_qk<<<288, 256>>>();
    k4_dw<<<1152, 256>>>(dw_w, off_lng, off_lnb);
    k5_off<<<384, 192>>>(off_b);
    k6_attn<<<1152, 256>>>(rpb, (float*)d_out);
}

// round 5
// speedup vs baseline: 1.6582x; 1.0836x over previous
#include <cuda_runtime.h>
#include <math.h>

#define HW       2304      // 48*48
#define NPIX     9216      // 96*96
#define XT_SLAB  294912    // 48*48*128
#define K_SLAB   73728     // 48*48*32

__device__ __align__(128) float g_xt [4*XT_SLAB];   // x channel-last per (b,g)
__device__ __align__(128) float g_k  [4*K_SLAB];    // k channel-last per (b,g)
__device__ __align__(128) float g_q  [4*K_SLAB];    // q lowres channel-last
__device__ __align__(128) float g_t  [4*NPIX*32];   // gelu(ln(dwconv(resize(q))))
__device__ __align__(128) float g_crd[4*NPIX*18];   // (iy,ix) per (bg,pix,tap)
__device__ float g_mu[2*HW], g_rstd[2*HW];
__device__ __align__(128) float g_WT[256*128];      // [c][o]; o<64: Wq, o>=64: Wk (LN-gain folded)
__device__ float g_csum[128], g_bias2[128];
__device__ __align__(128) float g_w2[2*9*9*32];     // [half][k][j][c]

// ---------------- k0: fold LN into weights (parallel), transpose offset weights
__global__ void k0_prep(const float* __restrict__ Wq, const float* __restrict__ Wk,
                        const float* __restrict__ g, const float* __restrict__ b,
                        const float* __restrict__ off_w)
{
    if (blockIdx.x >= 128) {
        int i = (blockIdx.x - 128)*256 + threadIdx.x;
        if (i < 2*9*9*32) {
            int c = i & 31; int j = (i >> 5) % 9; int k = (i/288) % 9; int half = i/2592;
            g_w2[i] = off_w[((j*2+half)*32 + c)*9 + k];
        }
        return;
    }
    int o = blockIdx.x, c = threadIdx.x;            // 256 threads, one per input channel
    const float* Wr = (o < 64) ? (Wq + o*256) : (Wk + (o-64)*256);
    float w  = Wr[c];
    float gc = g[c];
    g_WT[c*128 + o] = w*gc;
    float cs = w*gc, bs = w*b[c];
    #pragma unroll
    for (int off = 16; off; off >>= 1) {
        cs += __shfl_xor_sync(0xffffffffu, cs, off);
        bs += __shfl_xor_sync(0xffffffffu, bs, off);
    }
    __shared__ float scs[8], sbs[8];
    int wid = c >> 5, lane = c & 31;
    if (lane == 0) { scs[wid] = cs; sbs[wid] = bs; }
    __syncthreads();
    if (c == 0) {
        float a = 0.f, bbv = 0.f;
        #pragma unroll
        for (int i = 0; i < 8; i++) { a += scs[i]; bbv += sbs[i]; }
        g_csum[o] = a; g_bias2[o] = bbv;
    }
}

// ---------------- k1: transpose x to channel-last + LN stats ------------------
__global__ void k1_tr(const float* __restrict__ x)
{
    __shared__ float xs[128*49];
    __shared__ float ssum[48], ssq[48];
    int b = blockIdx.x / 48, y = blockIdx.x % 48;
    int t = threadIdx.x; // 256
    if (t < 48) { ssum[t] = 0.f; ssq[t] = 0.f; }
    int wid = t >> 5, lane = t & 31;
    for (int half = 0; half < 2; half++) {
        __syncthreads();
        const float* src = x + ((size_t)(b*256 + half*128))*HW + y*48;
        for (int idx = t; idx < 128*48; idx += 256) {
            int c = idx / 48, xx = idx - c*48;
            xs[c*49 + xx] = src[(size_t)c*HW + xx];
        }
        __syncthreads();
        for (int xx = wid; xx < 48; xx += 8) {
            float s = 0.f, q = 0.f;
            #pragma unroll
            for (int j = 0; j < 4; j++) { float v = xs[(lane + 32*j)*49 + xx]; s += v; q += v*v; }
            #pragma unroll
            for (int o = 16; o; o >>= 1) { s += __shfl_xor_sync(0xffffffffu, s, o); q += __shfl_xor_sync(0xffffffffu, q, o); }
            if (lane == 0) { ssum[xx] += s; ssq[xx] += q; }
        }
        float* dst = g_xt + ((size_t)(b*2 + half))*XT_SLAB + (size_t)y*48*128;
        for (int idx = t; idx < 128*48; idx += 256) {
            int xx = idx >> 7, c = idx & 127;
            dst[xx*128 + c] = xs[c*49 + xx];
        }
    }
    __syncthreads();
    if (t < 48) {
        float mu = ssum[t] * (1.0f/256.0f);
        float var = ssq[t] * (1.0f/256.0f) - mu*mu;
        int p = b*HW + y*48 + t;
        g_mu[p] = mu;
        g_rstd[p] = rsqrtf(var + 1e-5f);
    }
}

// ---------------- k2: Q/K projection (1px x 8out, float4 x loads) -------------
__global__ void k2_qk()
{
    int t = threadIdx.x;                 // 256
    int og = t & 15, pg = t >> 4;
    int P = blockIdx.x*16 + pg;          // 0..4607 (b,pixel)
    int b = P / HW, p = P % HW;
    int o0 = og*8;
    const float* x0 = g_xt + (size_t)(b*2)*XT_SLAB + (size_t)p*128;
    float acc[8];
    #pragma unroll
    for (int j = 0; j < 8; j++) acc[j] = 0.f;

    for (int h2 = 0; h2 < 2; h2++) {
        const float4* xp = (const float4*)(x0 + (size_t)h2*XT_SLAB);
        #pragma unroll 4
        for (int c4 = 0; c4 < 32; c4++) {
            float4 xv = xp[c4];
            const float* wb = &g_WT[(h2*128 + c4*4)*128 + o0];
            float4 w0, w1;
            w0 = *(const float4*)&wb[0];     w1 = *(const float4*)&wb[4];
            acc[0] += xv.x*w0.x; acc[1] += xv.x*w0.y; acc[2] += xv.x*w0.z; acc[3] += xv.x*w0.w;
            acc[4] += xv.x*w1.x; acc[5] += xv.x*w1.y; acc[6] += xv.x*w1.z; acc[7] += xv.x*w1.w;
            w0 = *(const float4*)&wb[128];   w1 = *(const float4*)&wb[132];
            acc[0] += xv.y*w0.x; acc[1] += xv.y*w0.y; acc[2] += xv.y*w0.z; acc[3] += xv.y*w0.w;
            acc[4] += xv.y*w1.x; acc[5] += xv.y*w1.y; acc[6] += xv.y*w1.z; acc[7] += xv.y*w1.w;
            w0 = *(const float4*)&wb[256];   w1 = *(const float4*)&wb[260];
            acc[0] += xv.z*w0.x; acc[1] += xv.z*w0.y; acc[2] += xv.z*w0.z; acc[3] += xv.z*w0.w;
            acc[4] += xv.z*w1.x; acc[5] += xv.z*w1.y; acc[6] += xv.z*w1.z; acc[7] += xv.z*w1.w;
            w0 = *(const float4*)&wb[384];   w1 = *(const float4*)&wb[388];
            acc[0] += xv.w*w0.x; acc[1] += xv.w*w0.y; acc[2] += xv.w*w0.z; acc[3] += xv.w*w0.w;
            acc[4] += xv.w*w1.x; acc[5] += xv.w*w1.y; acc[6] += xv.w*w1.z; acc[7] += xv.w*w1.w;
        }
    }
    float mu = g_mu[b*HW + p], rs = g_rstd[b*HW + p];
    float4 v0, v1;
    v0.x = rs*(acc[0] - mu*g_csum[o0+0]) + g_bias2[o0+0];
    v0.y = rs*(acc[1] - mu*g_csum[o0+1]) + g_bias2[o0+1];
    v0.z = rs*(acc[2] - mu*g_csum[o0+2]) + g_bias2[o0+2];
    v0.w = rs*(acc[3] - mu*g_csum[o0+3]) + g_bias2[o0+3];
    v1.x = rs*(acc[4] - mu*g_csum[o0+4]) + g_bias2[o0+4];
    v1.y = rs*(acc[5] - mu*g_csum[o0+5]) + g_bias2[o0+5];
    v1.z = rs*(acc[6] - mu*g_csum[o0+6]) + g_bias2[o0+6];
    v1.w = rs*(acc[7] - mu*g_csum[o0+7]) + g_bias2[o0+7];
    int isK = (o0 >= 64);
    int oo  = o0 & 63;
    int grp = oo >> 5, cl0 = oo & 31;
    float* dst = (isK ? g_k : g_q) + (size_t)(b*2 + grp)*K_SLAB + (size_t)p*32;
    *(float4*)&dst[cl0]     = v0;
    *(float4*)&dst[cl0 + 4] = v1;
}

// ---------------- k4: inline resize + depthwise 3x3 + channel-LN + GeLU -------
__global__ void k4_dw(const float* __restrict__ dw_w,
                      const float* __restrict__ offg, const float* __restrict__ offb)
{
    __shared__ float sq[102*32];         // 13 KB, [pos][c]
    int bid = blockIdx.x;                // 1152: bg*288 + oy*3 + xc
    int bg = bid / 288; int rem = bid % 288; int oy = rem / 3; int xc = rem % 3;
    int xbase = xc*32;
    const float* qb = g_q + (size_t)bg*K_SLAB;
    int t = threadIdx.x;                 // 256
    int w = t >> 5, lane = t & 31;
    const float R = 47.0f/95.0f;
    // warp-uniform tile fill: one warp per position, lane = channel
    for (int r = w; r < 102; r += 8) {
        int dy = (r >= 68) ? 2 : ((r >= 34) ? 1 : 0);
        int xx = r - dy*34;
        int ny = oy + dy - 1;
        int gx = xbase + xx - 1;
        float v = 0.f;
        if (((unsigned)ny < 96u) & ((unsigned)gx < 96u)) {
            float ysf = ny*R, xsf = gx*R;
            int y0 = min((int)ysf, 46), x0 = min((int)xsf, 46);
            float wy = ysf - (float)y0, wx = xsf - (float)x0;
            int b00 = (y0*48 + x0)*32 + lane;
            float qa = qb[b00], qbv = qb[b00+32], qc = qb[b00+1536], qd = qb[b00+1568];
            v = qa*(1.f-wy)*(1.f-wx) + qbv*(1.f-wy)*wx + qc*wy*(1.f-wx) + qd*wy*wx;
        }
        sq[r*32 + lane] = v;
    }
    __syncthreads();
    float wreg[9];
    #pragma unroll
    for (int k = 0; k < 9; k++) wreg[k] = dw_w[lane*9 + k];
    float lg = offg[lane], lb = offb[lane];
    #pragma unroll
    for (int pp = 0; pp < 4; pp++) {
        int lx = w*4 + pp;               // 0..31 local x
        float acc = 0.f;
        #pragma unroll
        for (int ky = 0; ky < 3; ky++)
            #pragma unroll
            for (int kx = 0; kx < 3; kx++)
                acc += sq[(ky*34 + lx + kx)*32 + lane] * wreg[ky*3+kx];
        float s = acc, q = acc*acc;
        #pragma unroll
        for (int o = 16; o; o >>= 1) { s += __shfl_xor_sync(0xffffffffu, s, o); q += __shfl_xor_sync(0xffffffffu, q, o); }
        float mu = s*(1.f/32.f);
        float var = q*(1.f/32.f) - mu*mu;
        float rs = rsqrtf(var + 1e-5f);
        float v = (acc - mu)*rs*lg + lb;
        float ge = 0.5f*v*(1.f + erff(v*0.70710678118654752f));
        g_t[(size_t)bg*NPIX*32 + (oy*96 + xbase + lx)*32 + lane] = ge;
    }
}

// ---------------- k5: offset conv 3x3 (32->18) + coords -----------------------
// 384 threads: px = t>>2, half = t&1, chalf = (t>>1)&1 (c-split, shfl-combined)
__global__ void k5_off(const float* __restrict__ off_b)
{
    __shared__ float st[294*36];         // 42.3 KB, [pos][c] pad36
    __shared__ float sw[2*9*9*32];       // 20.7 KB, [half][k][j][c]
    int bid = blockIdx.x;                // 384: bg*96 + oy
    int bg = bid / 96; int oy = bid % 96;
    int t = threadIdx.x;                 // 384
    int wid = t >> 5, lane = t & 31;
    const float* src = g_t + (size_t)bg*NPIX*32;
    for (int r = wid; r < 294; r += 12) {
        int dy = (r >= 196) ? 2 : ((r >= 98) ? 1 : 0);
        int xx = r - dy*98;
        int gx = xx - 1;
        int ny = oy + dy - 1;
        float v = 0.f;
        if (((unsigned)ny < 96u) & ((unsigned)gx < 96u)) v = src[(ny*96+gx)*32 + lane];
        st[r*36 + lane] = v;
    }
    for (int i = t; i < 2*9*9*32; i += 384) sw[i] = g_w2[i];
    __syncthreads();
    int px = t >> 2, half = t & 1, chalf = (t >> 1) & 1;
    float acc[9];
    #pragma unroll
    for (int j = 0; j < 9; j++) acc[j] = 0.f;

    #pragma unroll
    for (int c4 = 0; c4 < 4; c4++) {
        int c0 = chalf*16 + c4*4;
        #pragma unroll
        for (int k = 0; k < 9; k++) {
            float4 tv = *(const float4*)&st[((k/3)*98 + px + (k%3))*36 + c0];
            #pragma unroll
            for (int j = 0; j < 9; j++) {
                float4 wv = *(const float4*)&sw[((half*9 + k)*9 + j)*32 + c0];
                acc[j] += tv.x*wv.x + tv.y*wv.y + tv.z*wv.z + tv.w*wv.w;
            }
        }
    }
    #pragma unroll
    for (int j = 0; j < 9; j++) acc[j] += __shfl_xor_sync(0xffffffffu, acc[j], 2);
    if (chalf == 0) {
        const float R = 47.0f/95.0f;
        int p = oy*96 + px;
        #pragma unroll
        for (int j = 0; j < 9; j++) {
            float pred = acc[j] + off_b[j*2 + half];
            float o = tanhf(pred)*11.0f;
            float base = (half == 0) ? (float)(j/3 - 1) : (float)(j%3 - 1);
            float pix  = o + base + (half == 0 ? (float)oy : (float)px);
            g_crd[(((size_t)bg*NPIX + p)*9 + j)*2 + half] = pix * R;
        }
    }
}

// ---------------- k6: deformable attention (4 px/warp, 8 lanes/px) ------------
__global__ void k6_attn(const float* __restrict__ rpb, float* __restrict__ out)
{
    __shared__ float so[128*33];         // [ch][px], 16.9 KB
    int bid = blockIdx.x;                // 1152 blocks * 32 px
    int w = threadIdx.x >> 5, lane = threadIdx.x & 31;
    int sub = lane >> 3, ll = lane & 7;
    int bh = bid / 288; int b = bh >> 1, h = bh & 1;
    int prel0 = (bid % 288) * 32;
    int prel = prel0 + w*4 + sub;
    const float* kbase = g_k  + (size_t)bh*K_SLAB;
    const float* vbase = g_xt + (size_t)bh*XT_SLAB;
    const float* cp = g_crd + (size_t)bh*NPIX*18 + (size_t)prel*18;

    // inline q resize for this pixel (8 lanes x float4 = 32 ch)
    const float R = 47.0f/95.0f;
    int oy = prel / 96, ox = prel % 96;
    float ys = oy*R, xs = ox*R;
    int yq = min((int)ys, 46), xq = min((int)xs, 46);
    float wyq = ys - (float)yq, wxq = xs - (float)xq;
    const float* qb = g_q + (size_t)bh*K_SLAB;
    int q00 = (yq*48 + xq)*32 + ll*4;
    float4 qa = *(const float4*)&qb[q00];
    float4 qb2 = *(const float4*)&qb[q00+32];
    float4 qc = *(const float4*)&qb[q00+1536];
    float4 qd = *(const float4*)&qb[q00+1568];
    float a00 = (1.f-wyq)*(1.f-wxq), a01 = (1.f-wyq)*wxq, a10 = wyq*(1.f-wxq), a11 = wyq*wxq;
    const float S = 0.1767766952966369f;
    float4 qv;
    qv.x = (qa.x*a00 + qb2.x*a01 + qc.x*a10 + qd.x*a11)*S;
    qv.y = (qa.y*a00 + qb2.y*a01 + qc.y*a10 + qd.y*a11)*S;
    qv.z = (qa.z*a00 + qb2.z*a01 + qc.z*a10 + qd.z*a11)*S;
    qv.w = (qa.w*a00 + qb2.w*a01 + qc.w*a10 + qd.w*a11)*S;

    float a[9], wyA[9], wxA[9];
    int   pkA[9];
    float mx = -1e30f;
    #pragma unroll
    for (int j = 0; j < 9; j++) {
        float iy = cp[2*j], ix = cp[2*j+1];
        float y0f = floorf(iy), x0f = floorf(ix);
        float wy = iy - y0f, wx = ix - x0f;
        int y0 = (int)y0f, x0 = (int)x0f;
        wyA[j] = wy; wxA[j] = wx;
        pkA[j] = (y0 + 16) | ((x0 + 16) << 16);
        bool yi0 = (y0 >= 0) & (y0 < 48);
        bool yi1 = (y0 >= -1) & (y0 < 47);
        bool xi0 = (x0 >= 0) & (x0 < 48);
        bool xi1 = (x0 >= -1) & (x0 < 47);
        float w00 = (yi0 & xi0) ? (1.f-wy)*(1.f-wx) : 0.f;
        float w01 = (yi0 & xi1) ? (1.f-wy)*wx : 0.f;
        float w10 = (yi1 & xi0) ? wy*(1.f-wx) : 0.f;
        float w11 = (yi1 & xi1) ? wy*wx : 0.f;
        int yc0 = max(min(y0, 47), 0), yc1 = max(min(y0+1, 47), 0);
        int xc0 = max(min(x0, 47), 0), xc1 = max(min(x0+1, 47), 0);
        float4 c00 = *(const float4*)&kbase[(yc0*48+xc0)*32 + ll*4];
        float4 c01 = *(const float4*)&kbase[(yc0*48+xc1)*32 + ll*4];
        float4 c10 = *(const float4*)&kbase[(yc1*48+xc0)*32 + ll*4];
        float4 c11 = *(const float4*)&kbase[(yc1*48+xc1)*32 + ll*4];
        float4 rv = *(const float4*)&rpb[(h*9 + j)*32 + ll*4];
        float kx0 = c00.x*w00 + c01.x*w01 + c10.x*w10 + c11.x*w11 + rv.x;
        float kx1 = c00.y*w00 + c01.y*w01 + c10.y*w10 + c11.y*w11 + rv.y;
        float kx2 = c00.z*w00 + c01.z*w01 + c10.z*w10 + c11.z*w11 + rv.z;
        float kx3 = c00.w*w00 + c01.w*w01 + c10.w*w10 + c11.w*w11 + rv.w;
        float d = qv.x*kx0 + qv.y*kx1 + qv.z*kx2 + qv.w*kx3;
        d += __shfl_xor_sync(0xffffffffu, d, 4);
        d += __shfl_xor_sync(0xffffffffu, d, 2);
        d += __shfl_xor_sync(0xffffffffu, d, 1);
        a[j] = d;
        mx = fmaxf(mx, d);
    }
    float ssum = 0.f;
    #pragma unroll
    for (int j = 0; j < 9; j++) { a[j] = __expf(a[j] - mx); ssum += a[j]; }
    float inv = __fdividef(1.f, ssum);

    float4 acc[4];
    #pragma unroll
    for (int p2 = 0; p2 < 4; p2++) acc[p2] = make_float4(0.f, 0.f, 0.f, 0.f);

    #pragma unroll
    for (int j = 0; j < 9; j++) {
        int y0 = (pkA[j] & 0xffff) - 16;
        int x0 = (pkA[j] >> 16) - 16;
        float wy = wyA[j], wx = wxA[j];
        bool yi0 = (y0 >= 0) & (y0 < 48);
        bool yi1 = (y0 >= -1) & (y0 < 47);
        bool xi0 = (x0 >= 0) & (x0 < 48);
        bool xi1 = (x0 >= -1) & (x0 < 47);
        float aw = a[j]*inv;
        float w00 = (yi0 & xi0) ? aw*(1.f-wy)*(1.f-wx) : 0.f;
        float w01 = (yi0 & xi1) ? aw*(1.f-wy)*wx : 0.f;
        float w10 = (yi1 & xi0) ? aw*wy*(1.f-wx) : 0.f;
        float w11 = (yi1 & xi1) ? aw*wy*wx : 0.f;
        int yc0 = max(min(y0, 47), 0), yc1 = max(min(y0+1, 47), 0);
        int xc0 = max(min(x0, 47), 0), xc1 = max(min(x0+1, 47), 0);
        int r00 = (yc0*48+xc0)*128 + ll*4;
        int r01 = (yc0*48+xc1)*128 + ll*4;
        int r10 = (yc1*48+xc0)*128 + ll*4;
        int r11 = (yc1*48+xc1)*128 + ll*4;
        #pragma unroll
        for (int p2 = 0; p2 < 4; p2++) {
            float4 v00 = *(const float4*)&vbase[r00 + p2*32];
            float4 v01 = *(const float4*)&vbase[r01 + p2*32];
            float4 v10 = *(const float4*)&vbase[r10 + p2*32];
            float4 v11 = *(const float4*)&vbase[r11 + p2*32];
            acc[p2].x += w00*v00.x + w01*v01.x + w10*v10.x + w11*v11.x;
            acc[p2].y += w00*v00.y + w01*v01.y + w10*v10.y + w11*v11.y;
            acc[p2].z += w00*v00.z + w01*v01.z + w10*v10.z + w11*v11.z;
            acc[p2].w += w00*v00.w + w01*v01.w + w10*v10.w + w11*v11.w;
        }
    }
    // store to smem [ch][px] (conflict-free scalar STS)
    int pxl = w*4 + sub;
    #pragma unroll
    for (int p2 = 0; p2 < 4; p2++) {
        int ch = p2*32 + ll*4;
        so[(ch+0)*33 + pxl] = acc[p2].x;
        so[(ch+1)*33 + pxl] = acc[p2].y;
        so[(ch+2)*33 + pxl] = acc[p2].z;
        so[(ch+3)*33 + pxl] = acc[p2].w;
    }
    __syncthreads();
    float* ob = out + ((size_t)(b*256 + h*128))*NPIX + prel0;
    for (int idx = threadIdx.x; idx < 4096; idx += 256) {
        int ch = idx >> 5, px = idx & 31;
        ob[(size_t)ch*NPIX + px] = so[ch*33 + px];
    }
}

extern "C" void kernel_launch(void* const* d_in, const int* in_sizes, int n_in,
                              void* d_out, int out_size)
{
    const float* x       = (const float*)d_in[0];
    const float* ln_g    = (const float*)d_in[1];
    const float* ln_b    = (const float*)d_in[2];
    const float* Wq      = (const float*)d_in[3];
    const float* Wk      = (const float*)d_in[4];
    const float* dw_w    = (const float*)d_in[5];
    const float* off_lng = (const float*)d_in[6];
    const float* off_lnb = (const float*)d_in[7];
    const float* off_w   = (const float*)d_in[8];
    const float* off_b   = (const float*)d_in[9];
    const float* rpb     = (const float*)d_in[10];

    k0_prep<<<149, 256>>>(Wq, Wk, ln_g, ln_b, off_w);
    k1_tr<<<96, 256>>>(x);
    k2_qk<<<288, 256>>>();
    k4_dw<<<1152, 256>>>(dw_w, off_lng, off_lnb);
    k5_off<<<384, 384>>>(off_b);
    k6_attn<<<1152, 256>>>(rpb, (float*)d_out);
}